// round 4
// baseline (speedup 1.0000x reference)
#include <cuda_runtime.h>
#include <math.h>

// Problem constants (from reference_code)
#define NN   50000
#define EE   1600000
#define ENT  (EE + NN)     // edges incl. self-loops = 1650000
#define DIN  512
#define HH   256
#define GG   16

// ---------------- device scratch (static; no allocation allowed) ----------------
__device__ int   g_is64;                    // 1 if indices are int64, 0 if int32
__device__ int   g_cnt[NN];                 // degree (incl. self loop)
__device__ float g_dinv[NN];                // deg^{-1/2}
__device__ int   g_rowptr[NN + 1];          // CSR row pointers (by dst)
__device__ int   g_cursor[NN];              // fill cursors
__device__ int   g_col[ENT];                // CSR src indices
__device__ float g_w[ENT];                  // per-edge norm = dinv[s]*dinv[d]
__device__ float g_bufA[(size_t)NN * HH];   // transformed features (GEMM out)
__device__ float g_bufB[(size_t)NN * HH];   // aggregated features
__device__ float g_pooled[GG * HH];
__device__ int   g_gcount[GG];

// dtype-agnostic index load (flag-steered), clamped for crash-safety
__device__ __forceinline__ int load_idx(const void* p, long long i) {
    int v;
    if (g_is64) v = (int)((const long long*)p)[i];
    else        v = ((const int*)p)[i];
    return min(max(v, 0), NN - 1);
}
__device__ __forceinline__ int load_gidx(const void* p, long long i) {
    int v;
    if (g_is64) v = (int)((const long long*)p)[i];
    else        v = ((const int*)p)[i];
    return min(max(v, 0), GG - 1);
}

// ---------------- dtype probe ----------------
// int64 nonneg values < 2^31 -> odd 32-bit words all zero. int32 edge ids -> mostly nonzero.
__global__ void k_probe(const unsigned int* __restrict__ w) {
    __shared__ int any;
    if (threadIdx.x == 0) any = 0;
    __syncthreads();
    for (int i = threadIdx.x; i < 2048; i += 256)
        if (w[2 * i + 1] != 0u) atomicOr(&any, 1);
    __syncthreads();
    if (threadIdx.x == 0) g_is64 = (any == 0) ? 1 : 0;
}

// ---------------- setup kernels ----------------
__global__ void k_init_cnt() {
    int i = blockIdx.x * blockDim.x + threadIdx.x;
    if (i < NN) g_cnt[i] = 1;   // self-loop
}

__global__ void k_count(const void* __restrict__ ei) {
    int i = blockIdx.x * blockDim.x + threadIdx.x;
    if (i < EE) atomicAdd(&g_cnt[load_idx(ei, (long long)EE + i)], 1);
}

__global__ void k_dinv() {
    int i = blockIdx.x * blockDim.x + threadIdx.x;
    if (i < NN) {
        g_dinv[i]   = rsqrtf((float)g_cnt[i]);   // deg >= 1 always
        g_cursor[i] = 0;
    }
}

// single-block exclusive scan of g_cnt -> g_rowptr
__global__ void k_scan() {
    __shared__ int sh[1024];
    __shared__ int carry_sh;
    int tid = threadIdx.x;
    if (tid == 0) carry_sh = 0;
    __syncthreads();
    for (int base = 0; base < NN; base += 1024) {
        int i = base + tid;
        int v = (i < NN) ? g_cnt[i] : 0;
        sh[tid] = v;
        __syncthreads();
        #pragma unroll
        for (int off = 1; off < 1024; off <<= 1) {
            int tval = (tid >= off) ? sh[tid - off] : 0;
            __syncthreads();
            sh[tid] += tval;
            __syncthreads();
        }
        if (i < NN) g_rowptr[i] = carry_sh + sh[tid] - v;
        int total = sh[1023];
        __syncthreads();
        if (tid == 0) carry_sh += total;
        __syncthreads();
    }
    if (tid == 0) g_rowptr[NN] = carry_sh;   // == ENT
}

__global__ void k_fill(const void* __restrict__ ei) {
    int i = blockIdx.x * blockDim.x + threadIdx.x;
    if (i >= ENT) return;
    int s, d;
    if (i < EE) { s = load_idx(ei, i); d = load_idx(ei, (long long)EE + i); }
    else        { s = d = i - EE; }
    int pos = atomicAdd(&g_cursor[d], 1);
    int idx = g_rowptr[d] + pos;
    g_col[idx] = s;
    g_w[idx]   = g_dinv[s] * g_dinv[d];
}

// ---------------- fp32 GEMM: g_bufA[N,256] = A[N,K] @ B[K,256] ----------------
// 128x128 tile, BK=16, 256 threads, 8x8 micro-tile per thread.
// USE_GLOBAL_A=true -> A operand is g_bufB (ignore Aext); output always g_bufA.
template<int K, bool USE_GLOBAL_A>
__global__ __launch_bounds__(256) void k_gemm(const float* __restrict__ Aext,
                                              const float* __restrict__ B) {
    const int BM = 128, BN = 128, BK = 16;
    __shared__ float As[BK][BM + 4];   // stored k-major for broadcast reads
    __shared__ float Bs[BK][BN + 4];
    int t    = threadIdx.x;
    int col0 = blockIdx.x * BN;
    int row0 = blockIdx.y * BM;
    int tx   = t & 15;       // 16 col groups of 8
    int ty   = t >> 4;       // 16 row groups of 8

    const float* A = USE_GLOBAL_A ? (const float*)g_bufB : Aext;

    float acc[8][8];
    #pragma unroll
    for (int i = 0; i < 8; i++)
        #pragma unroll
        for (int j = 0; j < 8; j++) acc[i][j] = 0.f;

    for (int k0 = 0; k0 < K; k0 += BK) {
        // load A tile: 128x16 = 512 float4
        #pragma unroll
        for (int u = 0; u < 2; u++) {
            int idx = t + u * 256;       // 0..511
            int m   = idx >> 2;          // 0..127
            int kq  = idx & 3;           // which float4 along k
            float4 v = make_float4(0.f, 0.f, 0.f, 0.f);
            int gr = row0 + m;
            if (gr < NN)
                v = *(const float4*)(A + (size_t)gr * K + k0 + kq * 4);
            As[kq * 4 + 0][m] = v.x;
            As[kq * 4 + 1][m] = v.y;
            As[kq * 4 + 2][m] = v.z;
            As[kq * 4 + 3][m] = v.w;
        }
        // load B tile: 16x128 = 512 float4 (B rows are full 256-wide, always in-bounds)
        #pragma unroll
        for (int u = 0; u < 2; u++) {
            int idx = t + u * 256;
            int kk  = idx >> 5;          // 0..15
            int cq  = idx & 31;          // 0..31
            float4 v = *(const float4*)(B + (size_t)(k0 + kk) * HH + col0 + cq * 4);
            *(float4*)&Bs[kk][cq * 4] = v;
        }
        __syncthreads();
        #pragma unroll
        for (int k = 0; k < BK; k++) {
            float a[8], b[8];
            #pragma unroll
            for (int i = 0; i < 8; i++) a[i] = As[k][ty * 8 + i];
            #pragma unroll
            for (int j = 0; j < 8; j++) b[j] = Bs[k][tx * 8 + j];
            #pragma unroll
            for (int i = 0; i < 8; i++)
                #pragma unroll
                for (int j = 0; j < 8; j++)
                    acc[i][j] = fmaf(a[i], b[j], acc[i][j]);
        }
        __syncthreads();
    }
    #pragma unroll
    for (int i = 0; i < 8; i++) {
        int gr = row0 + ty * 8 + i;
        if (gr < NN) {
            float* cp = g_bufA + (size_t)gr * HH + col0 + tx * 8;
            *(float4*)(cp + 0) = make_float4(acc[i][0], acc[i][1], acc[i][2], acc[i][3]);
            *(float4*)(cp + 4) = make_float4(acc[i][4], acc[i][5], acc[i][6], acc[i][7]);
        }
    }
}

// ---------------- CSR gather aggregation: g_bufB[d] = sum_e w[e]*g_bufA[src[e]] + b ----------------
// one block per dst node; 256 threads = feature columns
template<int DO_RELU>
__global__ __launch_bounds__(256) void k_agg(const float* __restrict__ bias) {
    int n = blockIdx.x;
    int c = threadIdx.x;
    int start = g_rowptr[n];
    int end   = g_rowptr[n + 1];
    __shared__ int   scol[64];
    __shared__ float sw[64];
    const float* m = (const float*)g_bufA;
    float a0 = 0.f, a1 = 0.f, a2 = 0.f, a3 = 0.f;
    for (int e0 = start; e0 < end; e0 += 64) {
        int cnt = min(64, end - e0);
        if (c < cnt) { scol[c] = g_col[e0 + c]; sw[c] = g_w[e0 + c]; }
        __syncthreads();
        int j = 0;
        for (; j + 4 <= cnt; j += 4) {
            a0 = fmaf(__ldg(m + (size_t)scol[j + 0] * HH + c), sw[j + 0], a0);
            a1 = fmaf(__ldg(m + (size_t)scol[j + 1] * HH + c), sw[j + 1], a1);
            a2 = fmaf(__ldg(m + (size_t)scol[j + 2] * HH + c), sw[j + 2], a2);
            a3 = fmaf(__ldg(m + (size_t)scol[j + 3] * HH + c), sw[j + 3], a3);
        }
        for (; j < cnt; j++)
            a0 = fmaf(__ldg(m + (size_t)scol[j] * HH + c), sw[j], a0);
        __syncthreads();
    }
    float acc = (a0 + a1) + (a2 + a3) + bias[c];
    if (DO_RELU) acc = fmaxf(acc, 0.f);
    g_bufB[(size_t)n * HH + c] = acc;
}

// ---------------- pooling ----------------
__global__ void k_zero_pool() {
    int i = blockIdx.x * blockDim.x + threadIdx.x;
    if (i < GG * HH) g_pooled[i] = 0.f;
    if (i < GG) g_gcount[i] = 0;
}

// block = 64 nodes x 256 cols; batch sorted -> few boundaries per chunk
__global__ __launch_bounds__(256) void k_pool(const void* __restrict__ batch) {
    int base = blockIdx.x * 64;
    int c = threadIdx.x;
    __shared__ int sg[64];
    int nmax = min(64, NN - base);
    if (nmax <= 0) return;
    if (c < nmax) sg[c] = load_gidx(batch, base + c);
    __syncthreads();
    const float* h = (const float*)g_bufB;
    int gprev = sg[0];
    float acc = 0.f;
    for (int i = 0; i < nmax; i++) {
        int g = sg[i];
        if (g != gprev) {
            atomicAdd(&g_pooled[gprev * HH + c], acc);
            acc = 0.f;
            gprev = g;
        }
        acc += h[(size_t)(base + i) * HH + c];
    }
    atomicAdd(&g_pooled[gprev * HH + c], acc);
    if (c < nmax) atomicAdd(&g_gcount[sg[c]], 1);
}

// ---------------- final MLP + sigmoid (single block) ----------------
__global__ __launch_bounds__(1024) void k_mlp(const float* __restrict__ Wf,
                                              const float* __restrict__ bf,
                                              const float* __restrict__ Wp,
                                              const float* __restrict__ bp,
                                              float* __restrict__ out) {
    __shared__ float pm[GG * HH];      // pooled means
    __shared__ float fsh[GG * 64];
    int t = threadIdx.x;
    for (int i = t; i < GG * HH; i += 1024) {
        int g = i / HH;
        float cnt = fmaxf((float)g_gcount[g], 1.f);
        pm[i] = g_pooled[i] / cnt;
    }
    __syncthreads();
    int g  = t >> 6;    // 0..15
    int oc = t & 63;    // 0..63
    float f = bf[oc];
    #pragma unroll 8
    for (int k = 0; k < HH; k++)
        f = fmaf(pm[g * HH + k], Wf[k * 64 + oc], f);
    fsh[g * 64 + oc] = f;
    __syncthreads();
    if (t < GG) {
        float o = bp[0];
        #pragma unroll
        for (int j = 0; j < 64; j++)
            o = fmaf(fsh[t * 64 + j], Wp[j], o);
        out[t] = 1.f / (1.f + expf(-o));
    }
}

// ---------------- launch ----------------
extern "C" void kernel_launch(void* const* d_in, const int* in_sizes, int n_in,
                              void* d_out, int out_size) {
    const float* x     = (const float*)d_in[0];
    const void*  ei    = d_in[1];   // [2, E] int32 or int64 (probed on device)
    const void*  batch = d_in[2];
    const float* W1 = (const float*)d_in[3];
    const float* b1 = (const float*)d_in[4];
    const float* W2 = (const float*)d_in[5];
    const float* b2 = (const float*)d_in[6];
    const float* W3 = (const float*)d_in[7];
    const float* b3 = (const float*)d_in[8];
    const float* Wf = (const float*)d_in[9];
    const float* bf = (const float*)d_in[10];
    const float* Wp = (const float*)d_in[11];
    const float* bp = (const float*)d_in[12];
    float* out = (float*)d_out;

    // graph setup (recomputed each launch; deterministic work)
    k_probe<<<1, 256>>>((const unsigned int*)ei);
    k_init_cnt<<<(NN + 255) / 256, 256>>>();
    k_count<<<(EE + 255) / 256, 256>>>(ei);
    k_dinv<<<(NN + 255) / 256, 256>>>();
    k_scan<<<1, 1024>>>();
    k_fill<<<(ENT + 255) / 256, 256>>>(ei);

    dim3 ggrid(2, (NN + 127) / 128);  // 256/128 col tiles, 391 row tiles

    // layer 1: h = relu(Agg(x @ W1) + b1)
    k_gemm<DIN, false><<<ggrid, 256>>>(x, W1);
    k_agg<1><<<NN, 256>>>(b1);
    // layer 2
    k_gemm<HH, true><<<ggrid, 256>>>(nullptr, W2);
    k_agg<1><<<NN, 256>>>(b2);
    // layer 3 (no relu)
    k_gemm<HH, true><<<ggrid, 256>>>(nullptr, W3);
    k_agg<0><<<NN, 256>>>(b3);

    // pooling + head
    k_zero_pool<<<(GG * HH + 255) / 256, 256>>>();
    k_pool<<<(NN + 63) / 64, 256>>>(batch);
    k_mlp<<<1, 1024>>>(Wf, bf, Wp, bp, out);
}

// round 5
// speedup vs baseline: 1.3431x; 1.3431x over previous
#include <cuda_runtime.h>
#include <cuda_bf16.h>
#include <math.h>

// Problem constants (from reference_code)
#define NN   50000
#define EE   1600000
#define ENT  (EE + NN)     // edges incl. self-loops = 1650000
#define DIN  512
#define HH   256
#define GG   16

// ---------------- device scratch (static; no allocation allowed) ----------------
__device__ int   g_is64;                    // 1 if indices are int64, 0 if int32
__device__ int   g_cnt[NN];
__device__ float g_dinv[NN];
__device__ int   g_rowptr[NN + 1];
__device__ int   g_cursor[NN];
__device__ int   g_col[ENT];
__device__ float g_w[ENT];
__device__ float g_bufA[(size_t)NN * HH];   // GEMM output (transformed features)
__device__ float g_bufB[(size_t)NN * HH];   // aggregated features
__device__ float g_pooled[GG * HH];
__device__ int   g_gcount[GG];
// bf16 split operands
__device__ __nv_bfloat16 g_Ahi[(size_t)NN * DIN];
__device__ __nv_bfloat16 g_Alo[(size_t)NN * DIN];
__device__ __nv_bfloat16 g_Whi[DIN * HH];
__device__ __nv_bfloat16 g_Wlo[DIN * HH];

// dtype-agnostic index load (flag-steered), clamped for crash-safety
__device__ __forceinline__ int load_idx(const void* p, long long i) {
    int v;
    if (g_is64) v = (int)((const long long*)p)[i];
    else        v = ((const int*)p)[i];
    return min(max(v, 0), NN - 1);
}
__device__ __forceinline__ int load_gidx(const void* p, long long i) {
    int v;
    if (g_is64) v = (int)((const long long*)p)[i];
    else        v = ((const int*)p)[i];
    return min(max(v, 0), GG - 1);
}

// ---------------- dtype probe ----------------
__global__ void k_probe(const unsigned int* __restrict__ w) {
    __shared__ int any;
    if (threadIdx.x == 0) any = 0;
    __syncthreads();
    for (int i = threadIdx.x; i < 2048; i += 256)
        if (w[2 * i + 1] != 0u) atomicOr(&any, 1);
    __syncthreads();
    if (threadIdx.x == 0) g_is64 = (any == 0) ? 1 : 0;
}

// ---------------- setup kernels ----------------
__global__ void k_init_cnt() {
    int i = blockIdx.x * blockDim.x + threadIdx.x;
    if (i < NN) g_cnt[i] = 1;
}

__global__ void k_count(const void* __restrict__ ei) {
    int i = blockIdx.x * blockDim.x + threadIdx.x;
    if (i < EE) atomicAdd(&g_cnt[load_idx(ei, (long long)EE + i)], 1);
}

__global__ void k_dinv() {
    int i = blockIdx.x * blockDim.x + threadIdx.x;
    if (i < NN) {
        g_dinv[i]   = rsqrtf((float)g_cnt[i]);
        g_cursor[i] = 0;
    }
}

__global__ void k_scan() {
    __shared__ int sh[1024];
    __shared__ int carry_sh;
    int tid = threadIdx.x;
    if (tid == 0) carry_sh = 0;
    __syncthreads();
    for (int base = 0; base < NN; base += 1024) {
        int i = base + tid;
        int v = (i < NN) ? g_cnt[i] : 0;
        sh[tid] = v;
        __syncthreads();
        #pragma unroll
        for (int off = 1; off < 1024; off <<= 1) {
            int tval = (tid >= off) ? sh[tid - off] : 0;
            __syncthreads();
            sh[tid] += tval;
            __syncthreads();
        }
        if (i < NN) g_rowptr[i] = carry_sh + sh[tid] - v;
        int total = sh[1023];
        __syncthreads();
        if (tid == 0) carry_sh += total;
        __syncthreads();
    }
    if (tid == 0) g_rowptr[NN] = carry_sh;
}

__global__ void k_fill(const void* __restrict__ ei) {
    int i = blockIdx.x * blockDim.x + threadIdx.x;
    if (i >= ENT) return;
    int s, d;
    if (i < EE) { s = load_idx(ei, i); d = load_idx(ei, (long long)EE + i); }
    else        { s = d = i - EE; }
    int pos = atomicAdd(&g_cursor[d], 1);
    int idx = g_rowptr[d] + pos;
    g_col[idx] = s;
    g_w[idx]   = g_dinv[s] * g_dinv[d];
}

// ---------------- fp32 -> bf16 hi/lo split ----------------
// MODE: 0 = src -> Ahi/Alo ; 1 = g_bufB -> Ahi/Alo ; 2 = src -> Whi/Wlo
template<int MODE>
__global__ __launch_bounds__(256) void k_split(const float* __restrict__ srcExt, int n4) {
    int i = blockIdx.x * blockDim.x + threadIdx.x;
    if (i >= n4) return;
    const float* src = (MODE == 1) ? (const float*)g_bufB : srcExt;
    __nv_bfloat16* hi = (MODE == 2) ? g_Whi : g_Ahi;
    __nv_bfloat16* lo = (MODE == 2) ? g_Wlo : g_Alo;
    float4 v = ((const float4*)src)[i];
    __nv_bfloat16 h0 = __float2bfloat16(v.x);
    __nv_bfloat16 h1 = __float2bfloat16(v.y);
    __nv_bfloat16 h2 = __float2bfloat16(v.z);
    __nv_bfloat16 h3 = __float2bfloat16(v.w);
    __nv_bfloat16 l0 = __float2bfloat16(v.x - __bfloat162float(h0));
    __nv_bfloat16 l1 = __float2bfloat16(v.y - __bfloat162float(h1));
    __nv_bfloat16 l2 = __float2bfloat16(v.z - __bfloat162float(h2));
    __nv_bfloat16 l3 = __float2bfloat16(v.w - __bfloat162float(h3));
    __nv_bfloat162* hp = (__nv_bfloat162*)(hi + (size_t)i * 4);
    __nv_bfloat162* lp = (__nv_bfloat162*)(lo + (size_t)i * 4);
    hp[0] = __nv_bfloat162(h0, h1); hp[1] = __nv_bfloat162(h2, h3);
    lp[0] = __nv_bfloat162(l0, l1); lp[1] = __nv_bfloat162(l2, l3);
}

// ---------------- tensor-core GEMM ----------------
// g_bufA[N,256] = (Ahi+Alo)[N,K] @ (Whi+Wlo)[K,256], fp32 accum via 3x bf16 mma.
// BM=128, BN=128, BK=32; 256 threads = 8 warps in 2x4; per warp 64x32 (4 m16 x 4 n8).
__device__ __forceinline__ void ldsm_x4(unsigned* r, const void* p) {
    unsigned a = (unsigned)__cvta_generic_to_shared(p);
    asm volatile("ldmatrix.sync.aligned.m8n8.x4.shared.b16 {%0,%1,%2,%3}, [%4];"
                 : "=r"(r[0]), "=r"(r[1]), "=r"(r[2]), "=r"(r[3]) : "r"(a));
}
__device__ __forceinline__ void ldsm_x4t(unsigned* r, const void* p) {
    unsigned a = (unsigned)__cvta_generic_to_shared(p);
    asm volatile("ldmatrix.sync.aligned.m8n8.x4.trans.shared.b16 {%0,%1,%2,%3}, [%4];"
                 : "=r"(r[0]), "=r"(r[1]), "=r"(r[2]), "=r"(r[3]) : "r"(a));
}
__device__ __forceinline__ void mma_bf16(float* c, const unsigned* a, const unsigned* b) {
    asm volatile("mma.sync.aligned.m16n8k16.row.col.f32.bf16.bf16.f32 "
                 "{%0,%1,%2,%3}, {%4,%5,%6,%7}, {%8,%9}, {%0,%1,%2,%3};"
                 : "+f"(c[0]), "+f"(c[1]), "+f"(c[2]), "+f"(c[3])
                 : "r"(a[0]), "r"(a[1]), "r"(a[2]), "r"(a[3]), "r"(b[0]), "r"(b[1]));
}

#define ASTRIDE 40    // 32 + 8 pad (bf16)
#define BSTRIDE 136   // 128 + 8 pad (bf16)

template<int K>
__global__ __launch_bounds__(256) void k_gemm_mma() {
    __shared__ __nv_bfloat16 As_hi[128 * ASTRIDE];
    __shared__ __nv_bfloat16 As_lo[128 * ASTRIDE];
    __shared__ __nv_bfloat16 Bs_hi[32 * BSTRIDE];
    __shared__ __nv_bfloat16 Bs_lo[32 * BSTRIDE];

    int t      = threadIdx.x;
    int lane   = t & 31;
    int wid    = t >> 5;
    int warp_m = wid >> 2;       // 0..1 -> 64-row band
    int warp_n = wid & 3;        // 0..3 -> 32-col band
    int col0   = blockIdx.x * 128;
    int row0   = blockIdx.y * 128;

    float acc[4][4][4];
    #pragma unroll
    for (int mt = 0; mt < 4; mt++)
        #pragma unroll
        for (int nt = 0; nt < 4; nt++)
            #pragma unroll
            for (int r = 0; r < 4; r++) acc[mt][nt][r] = 0.f;

    for (int k0 = 0; k0 < K; k0 += 32) {
        // ---- load A tiles: 128 rows x 32 bf16 = 512 uint4 (hi & lo) ----
        #pragma unroll
        for (int u = 0; u < 2; u++) {
            int idx = t + u * 256;
            int m   = idx >> 2;          // 0..127
            int q   = idx & 3;           // which 8-bf16 chunk
            int gr  = row0 + m;
            uint4 vh = make_uint4(0u, 0u, 0u, 0u), vl = vh;
            if (gr < NN) {
                const uint4* ph = (const uint4*)(g_Ahi + (size_t)gr * K + k0 + q * 8);
                const uint4* pl = (const uint4*)(g_Alo + (size_t)gr * K + k0 + q * 8);
                vh = *ph; vl = *pl;
            }
            *(uint4*)(As_hi + m * ASTRIDE + q * 8) = vh;
            *(uint4*)(As_lo + m * ASTRIDE + q * 8) = vl;
        }
        // ---- load B tiles: 32 rows x 128 bf16 = 512 uint4 (hi & lo) ----
        #pragma unroll
        for (int u = 0; u < 2; u++) {
            int idx = t + u * 256;
            int kk  = idx >> 4;          // 0..31
            int q   = idx & 15;          // 0..15
            const uint4* ph = (const uint4*)(g_Whi + (size_t)(k0 + kk) * HH + col0 + q * 8);
            const uint4* pl = (const uint4*)(g_Wlo + (size_t)(k0 + kk) * HH + col0 + q * 8);
            *(uint4*)(Bs_hi + kk * BSTRIDE + q * 8) = *ph;
            *(uint4*)(Bs_lo + kk * BSTRIDE + q * 8) = *pl;
        }
        __syncthreads();

        #pragma unroll
        for (int ks = 0; ks < 2; ks++) {
            unsigned ah[4][4], al[4][4], bh[4][2], bl[4][2];
            // A fragments: 16x16 each, ldmatrix.x4
            int ar = lane & 15;          // row within 16
            int ac = (lane >> 4) * 8;    // k-half column
            #pragma unroll
            for (int mt = 0; mt < 4; mt++) {
                const __nv_bfloat16* pa = As_hi +
                    (warp_m * 64 + mt * 16 + ar) * ASTRIDE + ks * 16 + ac;
                ldsm_x4(ah[mt], pa);
                const __nv_bfloat16* pb = As_lo +
                    (warp_m * 64 + mt * 16 + ar) * ASTRIDE + ks * 16 + ac;
                ldsm_x4(al[mt], pb);
            }
            // B fragments: two n16 pairs via ldmatrix.x4.trans
            int bg  = lane >> 3;                         // 0..3 matrix group
            int brw = ks * 16 + (bg & 1) * 8 + (lane & 7);
            #pragma unroll
            for (int p = 0; p < 2; p++) {
                int bc = warp_n * 32 + p * 16 + (bg >> 1) * 8;
                unsigned tmp[4];
                ldsm_x4t(tmp, Bs_hi + brw * BSTRIDE + bc);
                bh[p * 2][0] = tmp[0]; bh[p * 2][1] = tmp[1];
                bh[p * 2 + 1][0] = tmp[2]; bh[p * 2 + 1][1] = tmp[3];
                ldsm_x4t(tmp, Bs_lo + brw * BSTRIDE + bc);
                bl[p * 2][0] = tmp[0]; bl[p * 2][1] = tmp[1];
                bl[p * 2 + 1][0] = tmp[2]; bl[p * 2 + 1][1] = tmp[3];
            }
            // 3-term split MMA
            #pragma unroll
            for (int mt = 0; mt < 4; mt++)
                #pragma unroll
                for (int nt = 0; nt < 4; nt++) {
                    mma_bf16(acc[mt][nt], ah[mt], bh[nt]);
                    mma_bf16(acc[mt][nt], ah[mt], bl[nt]);
                    mma_bf16(acc[mt][nt], al[mt], bh[nt]);
                }
        }
        __syncthreads();
    }

    // epilogue: fp32 store to g_bufA
    #pragma unroll
    for (int mt = 0; mt < 4; mt++) {
        int gr0 = row0 + warp_m * 64 + mt * 16 + (lane >> 2);
        #pragma unroll
        for (int nt = 0; nt < 4; nt++) {
            int gc = col0 + warp_n * 32 + nt * 8 + (lane & 3) * 2;
            if (gr0 < NN)
                *(float2*)(g_bufA + (size_t)gr0 * HH + gc) =
                    make_float2(acc[mt][nt][0], acc[mt][nt][1]);
            if (gr0 + 8 < NN)
                *(float2*)(g_bufA + (size_t)(gr0 + 8) * HH + gc) =
                    make_float2(acc[mt][nt][2], acc[mt][nt][3]);
        }
    }
}

// ---------------- CSR gather aggregation ----------------
template<int DO_RELU>
__global__ __launch_bounds__(256) void k_agg(const float* __restrict__ bias) {
    int n = blockIdx.x;
    int c = threadIdx.x;
    int start = g_rowptr[n];
    int end   = g_rowptr[n + 1];
    __shared__ int   scol[64];
    __shared__ float sw[64];
    const float* m = (const float*)g_bufA;
    float a0 = 0.f, a1 = 0.f, a2 = 0.f, a3 = 0.f;
    for (int e0 = start; e0 < end; e0 += 64) {
        int cnt = min(64, end - e0);
        if (c < cnt) { scol[c] = g_col[e0 + c]; sw[c] = g_w[e0 + c]; }
        __syncthreads();
        int j = 0;
        for (; j + 4 <= cnt; j += 4) {
            a0 = fmaf(__ldg(m + (size_t)scol[j + 0] * HH + c), sw[j + 0], a0);
            a1 = fmaf(__ldg(m + (size_t)scol[j + 1] * HH + c), sw[j + 1], a1);
            a2 = fmaf(__ldg(m + (size_t)scol[j + 2] * HH + c), sw[j + 2], a2);
            a3 = fmaf(__ldg(m + (size_t)scol[j + 3] * HH + c), sw[j + 3], a3);
        }
        for (; j < cnt; j++)
            a0 = fmaf(__ldg(m + (size_t)scol[j] * HH + c), sw[j], a0);
        __syncthreads();
    }
    float acc = (a0 + a1) + (a2 + a3) + bias[c];
    if (DO_RELU) acc = fmaxf(acc, 0.f);
    g_bufB[(size_t)n * HH + c] = acc;
}

// ---------------- pooling ----------------
__global__ void k_zero_pool() {
    int i = blockIdx.x * blockDim.x + threadIdx.x;
    if (i < GG * HH) g_pooled[i] = 0.f;
    if (i < GG) g_gcount[i] = 0;
}

__global__ __launch_bounds__(256) void k_pool(const void* __restrict__ batch) {
    int base = blockIdx.x * 64;
    int c = threadIdx.x;
    __shared__ int sg[64];
    int nmax = min(64, NN - base);
    if (nmax <= 0) return;
    if (c < nmax) sg[c] = load_gidx(batch, base + c);
    __syncthreads();
    const float* h = (const float*)g_bufB;
    int gprev = sg[0];
    float acc = 0.f;
    for (int i = 0; i < nmax; i++) {
        int g = sg[i];
        if (g != gprev) {
            atomicAdd(&g_pooled[gprev * HH + c], acc);
            acc = 0.f;
            gprev = g;
        }
        acc += h[(size_t)(base + i) * HH + c];
    }
    atomicAdd(&g_pooled[gprev * HH + c], acc);
    if (c < nmax) atomicAdd(&g_gcount[sg[c]], 1);
}

// ---------------- final MLP + sigmoid ----------------
__global__ __launch_bounds__(1024) void k_mlp(const float* __restrict__ Wf,
                                              const float* __restrict__ bf,
                                              const float* __restrict__ Wp,
                                              const float* __restrict__ bp,
                                              float* __restrict__ out) {
    __shared__ float pm[GG * HH];
    __shared__ float fsh[GG * 64];
    int t = threadIdx.x;
    for (int i = t; i < GG * HH; i += 1024) {
        int g = i / HH;
        float cnt = fmaxf((float)g_gcount[g], 1.f);
        pm[i] = g_pooled[i] / cnt;
    }
    __syncthreads();
    int g  = t >> 6;
    int oc = t & 63;
    float f = bf[oc];
    #pragma unroll 8
    for (int k = 0; k < HH; k++)
        f = fmaf(pm[g * HH + k], Wf[k * 64 + oc], f);
    fsh[g * 64 + oc] = f;
    __syncthreads();
    if (t < GG) {
        float o = bp[0];
        #pragma unroll
        for (int j = 0; j < 64; j++)
            o = fmaf(fsh[t * 64 + j], Wp[j], o);
        out[t] = 1.f / (1.f + expf(-o));
    }
}

// ---------------- launch ----------------
extern "C" void kernel_launch(void* const* d_in, const int* in_sizes, int n_in,
                              void* d_out, int out_size) {
    const float* x     = (const float*)d_in[0];
    const void*  ei    = d_in[1];   // [2, E] int32 or int64 (probed on device)
    const void*  batch = d_in[2];
    const float* W1 = (const float*)d_in[3];
    const float* b1 = (const float*)d_in[4];
    const float* W2 = (const float*)d_in[5];
    const float* b2 = (const float*)d_in[6];
    const float* W3 = (const float*)d_in[7];
    const float* b3 = (const float*)d_in[8];
    const float* Wf = (const float*)d_in[9];
    const float* bf = (const float*)d_in[10];
    const float* Wp = (const float*)d_in[11];
    const float* bp = (const float*)d_in[12];
    float* out = (float*)d_out;

    // graph setup
    k_probe<<<1, 256>>>((const unsigned int*)ei);
    k_init_cnt<<<(NN + 255) / 256, 256>>>();
    k_count<<<(EE + 255) / 256, 256>>>(ei);
    k_dinv<<<(NN + 255) / 256, 256>>>();
    k_scan<<<1, 1024>>>();
    k_fill<<<(ENT + 255) / 256, 256>>>(ei);

    dim3 ggrid(2, (NN + 127) / 128);
    const int nA1 = NN * DIN / 4, nA2 = NN * HH / 4;
    const int nW1 = DIN * HH / 4, nW2 = HH * HH / 4;

    // layer 1
    k_split<0><<<(nA1 + 255) / 256, 256>>>(x, nA1);
    k_split<2><<<(nW1 + 255) / 256, 256>>>(W1, nW1);
    k_gemm_mma<DIN><<<ggrid, 256>>>();
    k_agg<1><<<NN, 256>>>(b1);
    // layer 2
    k_split<1><<<(nA2 + 255) / 256, 256>>>(nullptr, nA2);
    k_split<2><<<(nW2 + 255) / 256, 256>>>(W2, nW2);
    k_gemm_mma<HH><<<ggrid, 256>>>();
    k_agg<1><<<NN, 256>>>(b2);
    // layer 3
    k_split<1><<<(nA2 + 255) / 256, 256>>>(nullptr, nA2);
    k_split<2><<<(nW2 + 255) / 256, 256>>>(W3, nW2);
    k_gemm_mma<HH><<<ggrid, 256>>>();
    k_agg<0><<<NN, 256>>>(b3);

    // pooling + head
    k_zero_pool<<<(GG * HH + 255) / 256, 256>>>();
    k_pool<<<(NN + 63) / 64, 256>>>(batch);
    k_mlp<<<1, 1024>>>(Wf, bf, Wp, bp, out);
}

// round 7
// speedup vs baseline: 2.0147x; 1.5000x over previous
#include <cuda_runtime.h>
#include <cuda_bf16.h>
#include <math.h>

// Problem constants (from reference_code)
#define NN   50000
#define EE   1600000
#define ENT  (EE + NN)     // edges incl. self-loops = 1650000
#define DIN  512
#define HH   256
#define GG   16

// ---------------- device scratch (static; no allocation allowed) ----------------
__device__ int   g_is64;                    // 1 if indices are int64, 0 if int32
__device__ int   g_cnt[NN];
__device__ float g_dinv[NN];
__device__ int   g_rowptr[NN + 1];
__device__ int   g_cursor[NN];
__device__ int   g_col[ENT];
__device__ float g_w[ENT];
__device__ float g_pooled[GG * HH];
__device__ int   g_gcount[GG];
// bf16 activation buffers
__device__ __nv_bfloat16 g_X16[(size_t)NN * DIN];  // bf16(x), layer-1 A operand
__device__ __nv_bfloat16 g_M16[(size_t)NN * HH];   // GEMM output (pre-aggregation)
__device__ __nv_bfloat16 g_H16[(size_t)NN * HH];   // agg output (next layer A operand)
// weight split (hi+lo keeps systematic weight error ~1e-5)
__device__ __nv_bfloat16 g_Whi[DIN * HH];
__device__ __nv_bfloat16 g_Wlo[DIN * HH];

// dtype-agnostic index load (flag-steered), clamped for crash-safety
__device__ __forceinline__ int load_idx(const void* p, long long i) {
    int v;
    if (g_is64) v = (int)((const long long*)p)[i];
    else        v = ((const int*)p)[i];
    return min(max(v, 0), NN - 1);
}
__device__ __forceinline__ int load_gidx(const void* p, long long i) {
    int v;
    if (g_is64) v = (int)((const long long*)p)[i];
    else        v = ((const int*)p)[i];
    return min(max(v, 0), GG - 1);
}

// ---------------- dtype probe ----------------
__global__ void k_probe(const unsigned int* __restrict__ w) {
    __shared__ int any;
    if (threadIdx.x == 0) any = 0;
    __syncthreads();
    for (int i = threadIdx.x; i < 2048; i += 256)
        if (w[2 * i + 1] != 0u) atomicOr(&any, 1);
    __syncthreads();
    if (threadIdx.x == 0) g_is64 = (any == 0) ? 1 : 0;
}

// ---------------- setup kernels ----------------
__global__ void k_init_cnt() {
    int i = blockIdx.x * blockDim.x + threadIdx.x;
    if (i < NN) g_cnt[i] = 1;
}

__global__ void k_count(const void* __restrict__ ei) {
    int i = blockIdx.x * blockDim.x + threadIdx.x;
    if (i < EE) atomicAdd(&g_cnt[load_idx(ei, (long long)EE + i)], 1);
}

__global__ void k_dinv() {
    int i = blockIdx.x * blockDim.x + threadIdx.x;
    if (i < NN) {
        g_dinv[i]   = rsqrtf((float)g_cnt[i]);
        g_cursor[i] = 0;
    }
}

__global__ void k_scan() {
    __shared__ int sh[1024];
    __shared__ int carry_sh;
    int tid = threadIdx.x;
    if (tid == 0) carry_sh = 0;
    __syncthreads();
    for (int base = 0; base < NN; base += 1024) {
        int i = base + tid;
        int v = (i < NN) ? g_cnt[i] : 0;
        sh[tid] = v;
        __syncthreads();
        #pragma unroll
        for (int off = 1; off < 1024; off <<= 1) {
            int tval = (tid >= off) ? sh[tid - off] : 0;
            __syncthreads();
            sh[tid] += tval;
            __syncthreads();
        }
        if (i < NN) g_rowptr[i] = carry_sh + sh[tid] - v;
        int total = sh[1023];
        __syncthreads();
        if (tid == 0) carry_sh += total;
        __syncthreads();
    }
    if (tid == 0) g_rowptr[NN] = carry_sh;
}

__global__ void k_fill(const void* __restrict__ ei) {
    int i = blockIdx.x * blockDim.x + threadIdx.x;
    if (i >= ENT) return;
    int s, d;
    if (i < EE) { s = load_idx(ei, i); d = load_idx(ei, (long long)EE + i); }
    else        { s = d = i - EE; }
    int pos = atomicAdd(&g_cursor[d], 1);
    int idx = g_rowptr[d] + pos;
    g_col[idx] = s;
    g_w[idx]   = g_dinv[s] * g_dinv[d];
}

// ---------------- converters ----------------
// x fp32 -> bf16 (hi only; node-feature error pools away)
__global__ __launch_bounds__(256) void k_x16(const float* __restrict__ src, int n4) {
    int i = blockIdx.x * blockDim.x + threadIdx.x;
    if (i >= n4) return;
    float4 v = ((const float4*)src)[i];
    __nv_bfloat162* p = (__nv_bfloat162*)(g_X16 + (size_t)i * 4);
    p[0] = __floats2bfloat162_rn(v.x, v.y);
    p[1] = __floats2bfloat162_rn(v.z, v.w);
}

// W fp32 -> hi/lo bf16 split (keeps systematic weight error ~1e-5)
__global__ __launch_bounds__(256) void k_wsplit(const float* __restrict__ src, int n4) {
    int i = blockIdx.x * blockDim.x + threadIdx.x;
    if (i >= n4) return;
    float4 v = ((const float4*)src)[i];
    __nv_bfloat16 h0 = __float2bfloat16(v.x);
    __nv_bfloat16 h1 = __float2bfloat16(v.y);
    __nv_bfloat16 h2 = __float2bfloat16(v.z);
    __nv_bfloat16 h3 = __float2bfloat16(v.w);
    __nv_bfloat162* hp = (__nv_bfloat162*)(g_Whi + (size_t)i * 4);
    __nv_bfloat162* lp = (__nv_bfloat162*)(g_Wlo + (size_t)i * 4);
    hp[0] = __nv_bfloat162(h0, h1); hp[1] = __nv_bfloat162(h2, h3);
    lp[0] = __floats2bfloat162_rn(v.x - __bfloat162float(h0), v.y - __bfloat162float(h1));
    lp[1] = __floats2bfloat162_rn(v.z - __bfloat162float(h2), v.w - __bfloat162float(h3));
}

// ---------------- tensor-core GEMM ----------------
// g_M16[N,256] = bf16: A[N,K] @ (Whi+Wlo)[K,256]; fp32 accum, 2 bf16 MMA terms.
__device__ __forceinline__ void ldsm_x4(unsigned* r, const void* p) {
    unsigned a = (unsigned)__cvta_generic_to_shared(p);
    asm volatile("ldmatrix.sync.aligned.m8n8.x4.shared.b16 {%0,%1,%2,%3}, [%4];"
                 : "=r"(r[0]), "=r"(r[1]), "=r"(r[2]), "=r"(r[3]) : "r"(a));
}
__device__ __forceinline__ void ldsm_x4t(unsigned* r, const void* p) {
    unsigned a = (unsigned)__cvta_generic_to_shared(p);
    asm volatile("ldmatrix.sync.aligned.m8n8.x4.trans.shared.b16 {%0,%1,%2,%3}, [%4];"
                 : "=r"(r[0]), "=r"(r[1]), "=r"(r[2]), "=r"(r[3]) : "r"(a));
}
__device__ __forceinline__ void mma_bf16(float* c, const unsigned* a, const unsigned* b) {
    asm volatile("mma.sync.aligned.m16n8k16.row.col.f32.bf16.bf16.f32 "
                 "{%0,%1,%2,%3}, {%4,%5,%6,%7}, {%8,%9}, {%0,%1,%2,%3};"
                 : "+f"(c[0]), "+f"(c[1]), "+f"(c[2]), "+f"(c[3])
                 : "r"(a[0]), "r"(a[1]), "r"(a[2]), "r"(a[3]), "r"(b[0]), "r"(b[1]));
}

#define ASTRIDE 40    // 32 + 8 pad (bf16)
#define BSTRIDE 136   // 128 + 8 pad (bf16)

// FIRST=true -> A = g_X16 (K=512); else A = g_H16 (K=256)
template<int K, bool FIRST>
__global__ __launch_bounds__(256) void k_gemm_mma() {
    __shared__ __nv_bfloat16 As[128 * ASTRIDE];
    __shared__ __nv_bfloat16 Bs_hi[32 * BSTRIDE];
    __shared__ __nv_bfloat16 Bs_lo[32 * BSTRIDE];

    int t      = threadIdx.x;
    int lane   = t & 31;
    int wid    = t >> 5;
    int warp_m = wid >> 2;       // 0..1 -> 64-row band
    int warp_n = wid & 3;        // 0..3 -> 32-col band
    int col0   = blockIdx.x * 128;
    int row0   = blockIdx.y * 128;

    const __nv_bfloat16* A = FIRST ? g_X16 : g_H16;

    float acc[4][4][4];
    #pragma unroll
    for (int mt = 0; mt < 4; mt++)
        #pragma unroll
        for (int nt = 0; nt < 4; nt++)
            #pragma unroll
            for (int r = 0; r < 4; r++) acc[mt][nt][r] = 0.f;

    for (int k0 = 0; k0 < K; k0 += 32) {
        // ---- load A tile: 128 rows x 32 bf16 = 512 uint4 ----
        #pragma unroll
        for (int u = 0; u < 2; u++) {
            int idx = t + u * 256;
            int m   = idx >> 2;
            int q   = idx & 3;
            int gr  = row0 + m;
            uint4 v = make_uint4(0u, 0u, 0u, 0u);
            if (gr < NN)
                v = *(const uint4*)(A + (size_t)gr * K + k0 + q * 8);
            *(uint4*)(As + m * ASTRIDE + q * 8) = v;
        }
        // ---- load B tiles: 32 rows x 128 bf16 (hi & lo) ----
        #pragma unroll
        for (int u = 0; u < 2; u++) {
            int idx = t + u * 256;
            int kk  = idx >> 4;
            int q   = idx & 15;
            *(uint4*)(Bs_hi + kk * BSTRIDE + q * 8) =
                *(const uint4*)(g_Whi + (size_t)(k0 + kk) * HH + col0 + q * 8);
            *(uint4*)(Bs_lo + kk * BSTRIDE + q * 8) =
                *(const uint4*)(g_Wlo + (size_t)(k0 + kk) * HH + col0 + q * 8);
        }
        __syncthreads();

        #pragma unroll
        for (int ks = 0; ks < 2; ks++) {
            unsigned ah[4][4], bh[4][2], bl[4][2];
            int ar = lane & 15;
            int ac = (lane >> 4) * 8;
            #pragma unroll
            for (int mt = 0; mt < 4; mt++)
                ldsm_x4(ah[mt], As + (warp_m * 64 + mt * 16 + ar) * ASTRIDE + ks * 16 + ac);
            int bg  = lane >> 3;
            int brw = ks * 16 + (bg & 1) * 8 + (lane & 7);
            #pragma unroll
            for (int p = 0; p < 2; p++) {
                int bc = warp_n * 32 + p * 16 + (bg >> 1) * 8;
                unsigned tmp[4];
                ldsm_x4t(tmp, Bs_hi + brw * BSTRIDE + bc);
                bh[p * 2][0] = tmp[0]; bh[p * 2][1] = tmp[1];
                bh[p * 2 + 1][0] = tmp[2]; bh[p * 2 + 1][1] = tmp[3];
                ldsm_x4t(tmp, Bs_lo + brw * BSTRIDE + bc);
                bl[p * 2][0] = tmp[0]; bl[p * 2][1] = tmp[1];
                bl[p * 2 + 1][0] = tmp[2]; bl[p * 2 + 1][1] = tmp[3];
            }
            #pragma unroll
            for (int mt = 0; mt < 4; mt++)
                #pragma unroll
                for (int nt = 0; nt < 4; nt++) {
                    mma_bf16(acc[mt][nt], ah[mt], bh[nt]);
                    mma_bf16(acc[mt][nt], ah[mt], bl[nt]);
                }
        }
        __syncthreads();
    }

    // epilogue: bf16 store to g_M16
    #pragma unroll
    for (int mt = 0; mt < 4; mt++) {
        int gr0 = row0 + warp_m * 64 + mt * 16 + (lane >> 2);
        #pragma unroll
        for (int nt = 0; nt < 4; nt++) {
            int gc = col0 + warp_n * 32 + nt * 8 + (lane & 3) * 2;
            if (gr0 < NN)
                *(__nv_bfloat162*)(g_M16 + (size_t)gr0 * HH + gc) =
                    __floats2bfloat162_rn(acc[mt][nt][0], acc[mt][nt][1]);
            if (gr0 + 8 < NN)
                *(__nv_bfloat162*)(g_M16 + (size_t)(gr0 + 8) * HH + gc) =
                    __floats2bfloat162_rn(acc[mt][nt][2], acc[mt][nt][3]);
        }
    }
}

// ---------------- CSR gather aggregation (bf16 in, bf16 out, fp32 accum) ----------------
// one block per dst node; 128 threads, each owns a bf162 column pair
template<int DO_RELU>
__global__ __launch_bounds__(128) void k_agg(const float* __restrict__ bias) {
    int n  = blockIdx.x;
    int c2 = threadIdx.x;            // 0..127 -> cols [2c2, 2c2+1]
    int start = g_rowptr[n];
    int end   = g_rowptr[n + 1];
    __shared__ int   scol[64];
    __shared__ float sw[64];
    const __nv_bfloat162* m = (const __nv_bfloat162*)g_M16;
    float2 a0 = make_float2(0.f, 0.f), a1 = a0, a2 = a0, a3 = a0;
    for (int e0 = start; e0 < end; e0 += 64) {
        int cnt = min(64, end - e0);
        if (c2 < cnt) { scol[c2] = g_col[e0 + c2]; sw[c2] = g_w[e0 + c2]; }
        __syncthreads();
        int j = 0;
        for (; j + 4 <= cnt; j += 4) {
            float2 v0 = __bfloat1622float2(__ldg(m + (size_t)scol[j + 0] * 128 + c2));
            float2 v1 = __bfloat1622float2(__ldg(m + (size_t)scol[j + 1] * 128 + c2));
            float2 v2 = __bfloat1622float2(__ldg(m + (size_t)scol[j + 2] * 128 + c2));
            float2 v3 = __bfloat1622float2(__ldg(m + (size_t)scol[j + 3] * 128 + c2));
            a0.x = fmaf(v0.x, sw[j + 0], a0.x); a0.y = fmaf(v0.y, sw[j + 0], a0.y);
            a1.x = fmaf(v1.x, sw[j + 1], a1.x); a1.y = fmaf(v1.y, sw[j + 1], a1.y);
            a2.x = fmaf(v2.x, sw[j + 2], a2.x); a2.y = fmaf(v2.y, sw[j + 2], a2.y);
            a3.x = fmaf(v3.x, sw[j + 3], a3.x); a3.y = fmaf(v3.y, sw[j + 3], a3.y);
        }
        for (; j < cnt; j++) {
            float2 v = __bfloat1622float2(__ldg(m + (size_t)scol[j] * 128 + c2));
            a0.x = fmaf(v.x, sw[j], a0.x); a0.y = fmaf(v.y, sw[j], a0.y);
        }
        __syncthreads();
    }
    float rx = (a0.x + a1.x) + (a2.x + a3.x) + bias[2 * c2];
    float ry = (a0.y + a1.y) + (a2.y + a3.y) + bias[2 * c2 + 1];
    if (DO_RELU) { rx = fmaxf(rx, 0.f); ry = fmaxf(ry, 0.f); }
    *(__nv_bfloat162*)(g_H16 + (size_t)n * HH + 2 * c2) = __floats2bfloat162_rn(rx, ry);
}

// ---------------- pooling ----------------
__global__ void k_zero_pool() {
    int i = blockIdx.x * blockDim.x + threadIdx.x;
    if (i < GG * HH) g_pooled[i] = 0.f;
    if (i < GG) g_gcount[i] = 0;
}

// block = 64 nodes x 128 col-pairs; batch sorted -> few boundaries per chunk
__global__ __launch_bounds__(128) void k_pool(const void* __restrict__ batch) {
    int base = blockIdx.x * 64;
    int c2 = threadIdx.x;
    __shared__ int sg[64];
    int nmax = min(64, NN - base);
    if (nmax <= 0) return;
    if (c2 < nmax) sg[c2] = load_gidx(batch, base + c2);
    __syncthreads();
    const __nv_bfloat162* h = (const __nv_bfloat162*)g_H16;
    int gprev = sg[0];
    float2 acc = make_float2(0.f, 0.f);
    for (int i = 0; i < nmax; i++) {
        int g = sg[i];
        if (g != gprev) {
            atomicAdd(&g_pooled[gprev * HH + 2 * c2], acc.x);
            atomicAdd(&g_pooled[gprev * HH + 2 * c2 + 1], acc.y);
            acc = make_float2(0.f, 0.f);
            gprev = g;
        }
        float2 v = __bfloat1622float2(h[(size_t)(base + i) * 128 + c2]);
        acc.x += v.x; acc.y += v.y;
    }
    atomicAdd(&g_pooled[gprev * HH + 2 * c2], acc.x);
    atomicAdd(&g_pooled[gprev * HH + 2 * c2 + 1], acc.y);
    if (c2 < nmax) atomicAdd(&g_gcount[sg[c2]], 1);
}

// ---------------- final MLP + sigmoid ----------------
__global__ __launch_bounds__(1024) void k_mlp(const float* __restrict__ Wf,
                                              const float* __restrict__ bf,
                                              const float* __restrict__ Wp,
                                              const float* __restrict__ bp,
                                              float* __restrict__ out) {
    __shared__ float pm[GG * HH];
    __shared__ float fsh[GG * 64];
    int t = threadIdx.x;
    for (int i = t; i < GG * HH; i += 1024) {
        int g = i / HH;
        float cnt = fmaxf((float)g_gcount[g], 1.f);
        pm[i] = g_pooled[i] / cnt;
    }
    __syncthreads();
    int g  = t >> 6;
    int oc = t & 63;
    float f = bf[oc];
    #pragma unroll 8
    for (int k = 0; k < HH; k++)
        f = fmaf(pm[g * HH + k], Wf[k * 64 + oc], f);
    fsh[g * 64 + oc] = f;
    __syncthreads();
    if (t < GG) {
        float o = bp[0];
        #pragma unroll
        for (int j = 0; j < 64; j++)
            o = fmaf(fsh[t * 64 + j], Wp[j], o);
        out[t] = 1.f / (1.f + expf(-o));
    }
}

// ---------------- launch ----------------
extern "C" void kernel_launch(void* const* d_in, const int* in_sizes, int n_in,
                              void* d_out, int out_size) {
    const float* x     = (const float*)d_in[0];
    const void*  ei    = d_in[1];   // [2, E] int32 or int64 (probed on device)
    const void*  batch = d_in[2];
    const float* W1 = (const float*)d_in[3];
    const float* b1 = (const float*)d_in[4];
    const float* W2 = (const float*)d_in[5];
    const float* b2 = (const float*)d_in[6];
    const float* W3 = (const float*)d_in[7];
    const float* b3 = (const float*)d_in[8];
    const float* Wf = (const float*)d_in[9];
    const float* bf = (const float*)d_in[10];
    const float* Wp = (const float*)d_in[11];
    const float* bp = (const float*)d_in[12];
    float* out = (float*)d_out;

    // graph setup
    k_probe<<<1, 256>>>((const unsigned int*)ei);
    k_init_cnt<<<(NN + 255) / 256, 256>>>();
    k_count<<<(EE + 255) / 256, 256>>>(ei);
    k_dinv<<<(NN + 255) / 256, 256>>>();
    k_scan<<<1, 1024>>>();
    k_fill<<<(ENT + 255) / 256, 256>>>(ei);

    dim3 ggrid(2, (NN + 127) / 128);
    const int nA1 = NN * DIN / 4;
    const int nW1 = DIN * HH / 4, nW2 = HH * HH / 4;

    k_x16<<<(nA1 + 255) / 256, 256>>>(x, nA1);

    // layer 1
    k_wsplit<<<(nW1 + 255) / 256, 256>>>(W1, nW1);
    k_gemm_mma<DIN, true><<<ggrid, 256>>>();
    k_agg<1><<<NN, 128>>>(b1);
    // layer 2
    k_wsplit<<<(nW2 + 255) / 256, 256>>>(W2, nW2);
    k_gemm_mma<HH, false><<<ggrid, 256>>>();
    k_agg<1><<<NN, 128>>>(b2);
    // layer 3
    k_wsplit<<<(nW2 + 255) / 256, 256>>>(W3, nW2);
    k_gemm_mma<HH, false><<<ggrid, 256>>>();
    k_agg<0><<<NN, 128>>>(b3);

    // pooling + head
    k_zero_pool<<<(GG * HH + 255) / 256, 256>>>();
    k_pool<<<(NN + 63) / 64, 128>>>(batch);
    k_mlp<<<1, 1024>>>(Wf, bf, Wp, bp, out);
}

// round 8
// speedup vs baseline: 2.2911x; 1.1372x over previous
#include <cuda_runtime.h>
#include <cuda_bf16.h>
#include <math.h>

// Problem constants (from reference_code)
#define NN   50000
#define EE   1600000
#define ENT  (EE + NN)     // edges incl. self-loops = 1650000
#define DIN  512
#define HH   256
#define GG   16
#define SCAN_B ((NN + 255) / 256)   // 196 scan blocks

// ---------------- device scratch (static; no allocation allowed) ----------------
__device__ int   g_is64;                    // 1 if indices are int64, 0 if int32
__device__ int   g_cnt[NN];
__device__ float g_dinv[NN];
__device__ int   g_rowptr[NN + 1];
__device__ int   g_cursor[NN];
__device__ int   g_bsum[SCAN_B];            // per-block partial sums
__device__ int   g_boff[SCAN_B];            // per-block exclusive offsets
__device__ int   g_col[ENT];
__device__ float g_w[ENT];
__device__ float g_pooled[GG * HH];
__device__ int   g_gcount[GG];
// bf16 buffers
__device__ __nv_bfloat16 g_X16[(size_t)NN * DIN];  // bf16(x), layer-1 A operand
__device__ __nv_bfloat16 g_M16[(size_t)NN * HH];   // GEMM output (pre-aggregation)
__device__ __nv_bfloat16 g_H16[(size_t)NN * HH];   // agg output (next layer A operand)
__device__ __nv_bfloat16 g_W16[DIN * HH];          // bf16 weights (current layer)

// dtype-agnostic index load (flag-steered), clamped for crash-safety
__device__ __forceinline__ int load_idx(const void* p, long long i) {
    int v;
    if (g_is64) v = (int)((const long long*)p)[i];
    else        v = ((const int*)p)[i];
    return min(max(v, 0), NN - 1);
}
__device__ __forceinline__ int load_gidx(const void* p, long long i) {
    int v;
    if (g_is64) v = (int)((const long long*)p)[i];
    else        v = ((const int*)p)[i];
    return min(max(v, 0), GG - 1);
}

// ---------------- dtype probe ----------------
__global__ void k_probe(const unsigned int* __restrict__ w) {
    __shared__ int any;
    if (threadIdx.x == 0) any = 0;
    __syncthreads();
    for (int i = threadIdx.x; i < 2048; i += 256)
        if (w[2 * i + 1] != 0u) atomicOr(&any, 1);
    __syncthreads();
    if (threadIdx.x == 0) g_is64 = (any == 0) ? 1 : 0;
}

// ---------------- setup kernels ----------------
__global__ void k_init_cnt() {
    int i = blockIdx.x * blockDim.x + threadIdx.x;
    if (i < NN) g_cnt[i] = 1;
}

__global__ void k_count(const void* __restrict__ ei) {
    int i = blockIdx.x * blockDim.x + threadIdx.x;
    if (i < EE) atomicAdd(&g_cnt[load_idx(ei, (long long)EE + i)], 1);
}

__global__ void k_dinv() {
    int i = blockIdx.x * blockDim.x + threadIdx.x;
    if (i < NN) {
        g_dinv[i]   = rsqrtf((float)g_cnt[i]);
        g_cursor[i] = 0;
    }
}

// ---- 3-phase parallel exclusive scan of g_cnt -> g_rowptr ----
__global__ void k_scan1() {
    __shared__ int sh[256];
    int t = threadIdx.x;
    int i = blockIdx.x * 256 + t;
    sh[t] = (i < NN) ? g_cnt[i] : 0;
    __syncthreads();
    #pragma unroll
    for (int off = 128; off > 0; off >>= 1) {
        if (t < off) sh[t] += sh[t + off];
        __syncthreads();
    }
    if (t == 0) g_bsum[blockIdx.x] = sh[0];
}

__global__ void k_scan2() {
    __shared__ int sh[256];
    int t = threadIdx.x;
    int v = (t < SCAN_B) ? g_bsum[t] : 0;
    sh[t] = v;
    __syncthreads();
    #pragma unroll
    for (int off = 1; off < 256; off <<= 1) {
        int tv = (t >= off) ? sh[t - off] : 0;
        __syncthreads();
        sh[t] += tv;
        __syncthreads();
    }
    if (t < SCAN_B) g_boff[t] = sh[t] - v;   // exclusive
    if (t == 255) g_rowptr[NN] = sh[255];    // == ENT
}

__global__ void k_scan3() {
    __shared__ int sh[256];
    int t = threadIdx.x;
    int i = blockIdx.x * 256 + t;
    int v = (i < NN) ? g_cnt[i] : 0;
    sh[t] = v;
    __syncthreads();
    #pragma unroll
    for (int off = 1; off < 256; off <<= 1) {
        int tv = (t >= off) ? sh[t - off] : 0;
        __syncthreads();
        sh[t] += tv;
        __syncthreads();
    }
    if (i < NN) g_rowptr[i] = g_boff[blockIdx.x] + sh[t] - v;
}

__global__ void k_fill(const void* __restrict__ ei) {
    int i = blockIdx.x * blockDim.x + threadIdx.x;
    if (i >= ENT) return;
    int s, d;
    if (i < EE) { s = load_idx(ei, i); d = load_idx(ei, (long long)EE + i); }
    else        { s = d = i - EE; }
    int pos = atomicAdd(&g_cursor[d], 1);
    int idx = g_rowptr[d] + pos;
    g_col[idx] = s;
    g_w[idx]   = g_dinv[s] * g_dinv[d];
}

// ---------------- converters ----------------
// fp32 -> bf16 (MODE 0: -> g_X16, MODE 1: -> g_W16)
template<int MODE>
__global__ __launch_bounds__(256) void k_cvt16(const float* __restrict__ src, int n4) {
    int i = blockIdx.x * blockDim.x + threadIdx.x;
    if (i >= n4) return;
    float4 v = ((const float4*)src)[i];
    __nv_bfloat16* dst = (MODE == 0) ? g_X16 : g_W16;
    __nv_bfloat162* p = (__nv_bfloat162*)(dst + (size_t)i * 4);
    p[0] = __floats2bfloat162_rn(v.x, v.y);
    p[1] = __floats2bfloat162_rn(v.z, v.w);
}

// ---------------- tensor-core GEMM ----------------
// g_M16[N,256] = bf16( A[N,K] @ W16[K,256] ); fp32 accum, single bf16 MMA term.
__device__ __forceinline__ void ldsm_x4(unsigned* r, const void* p) {
    unsigned a = (unsigned)__cvta_generic_to_shared(p);
    asm volatile("ldmatrix.sync.aligned.m8n8.x4.shared.b16 {%0,%1,%2,%3}, [%4];"
                 : "=r"(r[0]), "=r"(r[1]), "=r"(r[2]), "=r"(r[3]) : "r"(a));
}
__device__ __forceinline__ void ldsm_x4t(unsigned* r, const void* p) {
    unsigned a = (unsigned)__cvta_generic_to_shared(p);
    asm volatile("ldmatrix.sync.aligned.m8n8.x4.trans.shared.b16 {%0,%1,%2,%3}, [%4];"
                 : "=r"(r[0]), "=r"(r[1]), "=r"(r[2]), "=r"(r[3]) : "r"(a));
}
__device__ __forceinline__ void mma_bf16(float* c, const unsigned* a, const unsigned* b) {
    asm volatile("mma.sync.aligned.m16n8k16.row.col.f32.bf16.bf16.f32 "
                 "{%0,%1,%2,%3}, {%4,%5,%6,%7}, {%8,%9}, {%0,%1,%2,%3};"
                 : "+f"(c[0]), "+f"(c[1]), "+f"(c[2]), "+f"(c[3])
                 : "r"(a[0]), "r"(a[1]), "r"(a[2]), "r"(a[3]), "r"(b[0]), "r"(b[1]));
}

#define ASTRIDE 40    // 32 + 8 pad (bf16)
#define BSTRIDE 136   // 128 + 8 pad (bf16)

// FIRST=true -> A = g_X16 (K=512); else A = g_H16 (K=256)
template<int K, bool FIRST>
__global__ __launch_bounds__(256) void k_gemm_mma() {
    __shared__ __nv_bfloat16 As[128 * ASTRIDE];
    __shared__ __nv_bfloat16 Bs[32 * BSTRIDE];

    int t      = threadIdx.x;
    int lane   = t & 31;
    int wid    = t >> 5;
    int warp_m = wid >> 2;       // 0..1 -> 64-row band
    int warp_n = wid & 3;        // 0..3 -> 32-col band
    int col0   = blockIdx.x * 128;
    int row0   = blockIdx.y * 128;

    const __nv_bfloat16* A = FIRST ? g_X16 : g_H16;

    float acc[4][4][4];
    #pragma unroll
    for (int mt = 0; mt < 4; mt++)
        #pragma unroll
        for (int nt = 0; nt < 4; nt++)
            #pragma unroll
            for (int r = 0; r < 4; r++) acc[mt][nt][r] = 0.f;

    for (int k0 = 0; k0 < K; k0 += 32) {
        // ---- load A tile: 128 rows x 32 bf16 = 512 uint4 ----
        #pragma unroll
        for (int u = 0; u < 2; u++) {
            int idx = t + u * 256;
            int m   = idx >> 2;
            int q   = idx & 3;
            int gr  = row0 + m;
            uint4 v = make_uint4(0u, 0u, 0u, 0u);
            if (gr < NN)
                v = *(const uint4*)(A + (size_t)gr * K + k0 + q * 8);
            *(uint4*)(As + m * ASTRIDE + q * 8) = v;
        }
        // ---- load B tile: 32 rows x 128 bf16 = 512 uint4 ----
        #pragma unroll
        for (int u = 0; u < 2; u++) {
            int idx = t + u * 256;
            int kk  = idx >> 4;
            int q   = idx & 15;
            *(uint4*)(Bs + kk * BSTRIDE + q * 8) =
                *(const uint4*)(g_W16 + (size_t)(k0 + kk) * HH + col0 + q * 8);
        }
        __syncthreads();

        #pragma unroll
        for (int ks = 0; ks < 2; ks++) {
            unsigned ah[4][4], bh[4][2];
            int ar = lane & 15;
            int ac = (lane >> 4) * 8;
            #pragma unroll
            for (int mt = 0; mt < 4; mt++)
                ldsm_x4(ah[mt], As + (warp_m * 64 + mt * 16 + ar) * ASTRIDE + ks * 16 + ac);
            int bg  = lane >> 3;
            int brw = ks * 16 + (bg & 1) * 8 + (lane & 7);
            #pragma unroll
            for (int p = 0; p < 2; p++) {
                int bc = warp_n * 32 + p * 16 + (bg >> 1) * 8;
                unsigned tmp[4];
                ldsm_x4t(tmp, Bs + brw * BSTRIDE + bc);
                bh[p * 2][0] = tmp[0]; bh[p * 2][1] = tmp[1];
                bh[p * 2 + 1][0] = tmp[2]; bh[p * 2 + 1][1] = tmp[3];
            }
            #pragma unroll
            for (int mt = 0; mt < 4; mt++)
                #pragma unroll
                for (int nt = 0; nt < 4; nt++)
                    mma_bf16(acc[mt][nt], ah[mt], bh[nt]);
        }
        __syncthreads();
    }

    // epilogue: bf16 store to g_M16
    #pragma unroll
    for (int mt = 0; mt < 4; mt++) {
        int gr0 = row0 + warp_m * 64 + mt * 16 + (lane >> 2);
        #pragma unroll
        for (int nt = 0; nt < 4; nt++) {
            int gc = col0 + warp_n * 32 + nt * 8 + (lane & 3) * 2;
            if (gr0 < NN)
                *(__nv_bfloat162*)(g_M16 + (size_t)gr0 * HH + gc) =
                    __floats2bfloat162_rn(acc[mt][nt][0], acc[mt][nt][1]);
            if (gr0 + 8 < NN)
                *(__nv_bfloat162*)(g_M16 + (size_t)(gr0 + 8) * HH + gc) =
                    __floats2bfloat162_rn(acc[mt][nt][2], acc[mt][nt][3]);
        }
    }
}

// ---------------- CSR gather aggregation (bf16 in, bf16 out, fp32 accum) ----------------
// one block per dst node; 128 threads, each owns a bf162 column pair
template<int DO_RELU>
__global__ __launch_bounds__(128) void k_agg(const float* __restrict__ bias) {
    int n  = blockIdx.x;
    int c2 = threadIdx.x;            // 0..127 -> cols [2c2, 2c2+1]
    int start = g_rowptr[n];
    int end   = g_rowptr[n + 1];
    __shared__ int   scol[64];
    __shared__ float sw[64];
    const __nv_bfloat162* m = (const __nv_bfloat162*)g_M16;
    float2 a0 = make_float2(0.f, 0.f), a1 = a0, a2 = a0, a3 = a0;
    for (int e0 = start; e0 < end; e0 += 64) {
        int cnt = min(64, end - e0);
        if (c2 < cnt) { scol[c2] = g_col[e0 + c2]; sw[c2] = g_w[e0 + c2]; }
        __syncthreads();
        int j = 0;
        for (; j + 4 <= cnt; j += 4) {
            float2 v0 = __bfloat1622float2(__ldg(m + (size_t)scol[j + 0] * 128 + c2));
            float2 v1 = __bfloat1622float2(__ldg(m + (size_t)scol[j + 1] * 128 + c2));
            float2 v2 = __bfloat1622float2(__ldg(m + (size_t)scol[j + 2] * 128 + c2));
            float2 v3 = __bfloat1622float2(__ldg(m + (size_t)scol[j + 3] * 128 + c2));
            a0.x = fmaf(v0.x, sw[j + 0], a0.x); a0.y = fmaf(v0.y, sw[j + 0], a0.y);
            a1.x = fmaf(v1.x, sw[j + 1], a1.x); a1.y = fmaf(v1.y, sw[j + 1], a1.y);
            a2.x = fmaf(v2.x, sw[j + 2], a2.x); a2.y = fmaf(v2.y, sw[j + 2], a2.y);
            a3.x = fmaf(v3.x, sw[j + 3], a3.x); a3.y = fmaf(v3.y, sw[j + 3], a3.y);
        }
        for (; j < cnt; j++) {
            float2 v = __bfloat1622float2(__ldg(m + (size_t)scol[j] * 128 + c2));
            a0.x = fmaf(v.x, sw[j], a0.x); a0.y = fmaf(v.y, sw[j], a0.y);
        }
        __syncthreads();
    }
    float rx = (a0.x + a1.x) + (a2.x + a3.x) + bias[2 * c2];
    float ry = (a0.y + a1.y) + (a2.y + a3.y) + bias[2 * c2 + 1];
    if (DO_RELU) { rx = fmaxf(rx, 0.f); ry = fmaxf(ry, 0.f); }
    *(__nv_bfloat162*)(g_H16 + (size_t)n * HH + 2 * c2) = __floats2bfloat162_rn(rx, ry);
}

// ---------------- pooling ----------------
__global__ void k_zero_pool() {
    int i = blockIdx.x * blockDim.x + threadIdx.x;
    if (i < GG * HH) g_pooled[i] = 0.f;
    if (i < GG) g_gcount[i] = 0;
}

// block = 64 nodes x 128 col-pairs; batch sorted -> few boundaries per chunk
__global__ __launch_bounds__(128) void k_pool(const void* __restrict__ batch) {
    int base = blockIdx.x * 64;
    int c2 = threadIdx.x;
    __shared__ int sg[64];
    int nmax = min(64, NN - base);
    if (nmax <= 0) return;
    if (c2 < nmax) sg[c2] = load_gidx(batch, base + c2);
    __syncthreads();
    const __nv_bfloat162* h = (const __nv_bfloat162*)g_H16;
    int gprev = sg[0];
    float2 acc = make_float2(0.f, 0.f);
    for (int i = 0; i < nmax; i++) {
        int g = sg[i];
        if (g != gprev) {
            atomicAdd(&g_pooled[gprev * HH + 2 * c2], acc.x);
            atomicAdd(&g_pooled[gprev * HH + 2 * c2 + 1], acc.y);
            acc = make_float2(0.f, 0.f);
            gprev = g;
        }
        float2 v = __bfloat1622float2(h[(size_t)(base + i) * 128 + c2]);
        acc.x += v.x; acc.y += v.y;
    }
    atomicAdd(&g_pooled[gprev * HH + 2 * c2], acc.x);
    atomicAdd(&g_pooled[gprev * HH + 2 * c2 + 1], acc.y);
    if (c2 < nmax) atomicAdd(&g_gcount[sg[c2]], 1);
}

// ---------------- final MLP + sigmoid ----------------
__global__ __launch_bounds__(1024) void k_mlp(const float* __restrict__ Wf,
                                              const float* __restrict__ bf,
                                              const float* __restrict__ Wp,
                                              const float* __restrict__ bp,
                                              float* __restrict__ out) {
    __shared__ float pm[GG * HH];
    __shared__ float fsh[GG * 64];
    int t = threadIdx.x;
    for (int i = t; i < GG * HH; i += 1024) {
        int g = i / HH;
        float cnt = fmaxf((float)g_gcount[g], 1.f);
        pm[i] = g_pooled[i] / cnt;
    }
    __syncthreads();
    int g  = t >> 6;
    int oc = t & 63;
    float f = bf[oc];
    #pragma unroll 8
    for (int k = 0; k < HH; k++)
        f = fmaf(pm[g * HH + k], Wf[k * 64 + oc], f);
    fsh[g * 64 + oc] = f;
    __syncthreads();
    if (t < GG) {
        float o = bp[0];
        #pragma unroll
        for (int j = 0; j < 64; j++)
            o = fmaf(fsh[t * 64 + j], Wp[j], o);
        out[t] = 1.f / (1.f + expf(-o));
    }
}

// ---------------- launch ----------------
extern "C" void kernel_launch(void* const* d_in, const int* in_sizes, int n_in,
                              void* d_out, int out_size) {
    const float* x     = (const float*)d_in[0];
    const void*  ei    = d_in[1];   // [2, E] int32 or int64 (probed on device)
    const void*  batch = d_in[2];
    const float* W1 = (const float*)d_in[3];
    const float* b1 = (const float*)d_in[4];
    const float* W2 = (const float*)d_in[5];
    const float* b2 = (const float*)d_in[6];
    const float* W3 = (const float*)d_in[7];
    const float* b3 = (const float*)d_in[8];
    const float* Wf = (const float*)d_in[9];
    const float* bf = (const float*)d_in[10];
    const float* Wp = (const float*)d_in[11];
    const float* bp = (const float*)d_in[12];
    float* out = (float*)d_out;

    // graph setup
    k_probe<<<1, 256>>>((const unsigned int*)ei);
    k_init_cnt<<<SCAN_B, 256>>>();
    k_count<<<(EE + 255) / 256, 256>>>(ei);
    k_dinv<<<SCAN_B, 256>>>();
    k_scan1<<<SCAN_B, 256>>>();
    k_scan2<<<1, 256>>>();
    k_scan3<<<SCAN_B, 256>>>();
    k_fill<<<(ENT + 255) / 256, 256>>>(ei);

    dim3 ggrid(2, (NN + 127) / 128);
    const int nA1 = NN * DIN / 4;
    const int nW1 = DIN * HH / 4, nW2 = HH * HH / 4;

    k_cvt16<0><<<(nA1 + 255) / 256, 256>>>(x, nA1);

    // layer 1
    k_cvt16<1><<<(nW1 + 255) / 256, 256>>>(W1, nW1);
    k_gemm_mma<DIN, true><<<ggrid, 256>>>();
    k_agg<1><<<NN, 128>>>(b1);
    // layer 2
    k_cvt16<1><<<(nW2 + 255) / 256, 256>>>(W2, nW2);
    k_gemm_mma<HH, false><<<ggrid, 256>>>();
    k_agg<1><<<NN, 128>>>(b2);
    // layer 3
    k_cvt16<1><<<(nW2 + 255) / 256, 256>>>(W3, nW2);
    k_gemm_mma<HH, false><<<ggrid, 256>>>();
    k_agg<0><<<NN, 128>>>(b3);

    // pooling + head
    k_zero_pool<<<(GG * HH + 255) / 256, 256>>>();
    k_pool<<<(NN + 63) / 64, 128>>>(batch);
    k_mlp<<<1, 1024>>>(Wf, bf, Wp, bp, out);
}

// round 10
// speedup vs baseline: 2.6665x; 1.1639x over previous
#include <cuda_runtime.h>
#include <cuda_bf16.h>
#include <cuda_fp16.h>
#include <cuda_fp8.h>
#include <math.h>

// Problem constants (from reference_code)
#define NN   50000
#define EE   1600000
#define ENT  (EE + NN)     // edges incl. self-loops = 1650000
#define DIN  512
#define HH   256
#define GG   16
#define SCAN_B ((NN + 255) / 256)   // 196 scan blocks

// ---------------- device scratch (static; no allocation allowed) ----------------
__device__ int   g_is64;                    // 1 if indices are int64, 0 if int32
__device__ int   g_cnt[NN];
__device__ float g_dinv[NN];
__device__ int   g_rowptr[NN + 1];
__device__ int   g_cursor[NN];
__device__ int   g_bsum[SCAN_B];            // per-block partial sums
__device__ int   g_boff[SCAN_B];            // per-block exclusive offsets
__device__ int   g_col[ENT];
__device__ float g_w[ENT];
__device__ float g_pooled[GG * HH];
__device__ int   g_gcount[GG];
// buffers
__device__ __nv_bfloat16 g_X16[(size_t)NN * DIN];  // bf16(x), layer-1 A operand
__device__ unsigned char g_M8[(size_t)NN * HH];    // GEMM output, e4m3 (gather input)
__device__ __nv_bfloat16 g_H16[(size_t)NN * HH];   // agg output (next layer A operand)
__device__ __nv_bfloat16 g_W16[DIN * HH];          // bf16 weights (current layer)

// dtype-agnostic index load (flag-steered), clamped for crash-safety
__device__ __forceinline__ int load_idx(const void* p, long long i) {
    int v;
    if (g_is64) v = (int)((const long long*)p)[i];
    else        v = ((const int*)p)[i];
    return min(max(v, 0), NN - 1);
}
__device__ __forceinline__ int load_gidx(const void* p, long long i) {
    int v;
    if (g_is64) v = (int)((const long long*)p)[i];
    else        v = ((const int*)p)[i];
    return min(max(v, 0), GG - 1);
}

// ---------------- dtype probe ----------------
__global__ void k_probe(const unsigned int* __restrict__ w) {
    __shared__ int any;
    if (threadIdx.x == 0) any = 0;
    __syncthreads();
    for (int i = threadIdx.x; i < 2048; i += 256)
        if (w[2 * i + 1] != 0u) atomicOr(&any, 1);
    __syncthreads();
    if (threadIdx.x == 0) g_is64 = (any == 0) ? 1 : 0;
}

// ---------------- setup kernels ----------------
__global__ void k_init_cnt() {
    int i = blockIdx.x * blockDim.x + threadIdx.x;
    if (i < NN) g_cnt[i] = 1;
}

__global__ void k_count(const void* __restrict__ ei) {
    int i = blockIdx.x * blockDim.x + threadIdx.x;
    if (i < EE) atomicAdd(&g_cnt[load_idx(ei, (long long)EE + i)], 1);
}

__global__ void k_dinv() {
    int i = blockIdx.x * blockDim.x + threadIdx.x;
    if (i < NN) {
        g_dinv[i]   = rsqrtf((float)g_cnt[i]);
        g_cursor[i] = 0;
    }
}

// ---- 3-phase parallel exclusive scan of g_cnt -> g_rowptr ----
__global__ void k_scan1() {
    __shared__ int sh[256];
    int t = threadIdx.x;
    int i = blockIdx.x * 256 + t;
    sh[t] = (i < NN) ? g_cnt[i] : 0;
    __syncthreads();
    #pragma unroll
    for (int off = 128; off > 0; off >>= 1) {
        if (t < off) sh[t] += sh[t + off];
        __syncthreads();
    }
    if (t == 0) g_bsum[blockIdx.x] = sh[0];
}

__global__ void k_scan2() {
    __shared__ int sh[256];
    int t = threadIdx.x;
    int v = (t < SCAN_B) ? g_bsum[t] : 0;
    sh[t] = v;
    __syncthreads();
    #pragma unroll
    for (int off = 1; off < 256; off <<= 1) {
        int tv = (t >= off) ? sh[t - off] : 0;
        __syncthreads();
        sh[t] += tv;
        __syncthreads();
    }
    if (t < SCAN_B) g_boff[t] = sh[t] - v;   // exclusive
    if (t == 255) g_rowptr[NN] = sh[255];    // == ENT
}

__global__ void k_scan3() {
    __shared__ int sh[256];
    int t = threadIdx.x;
    int i = blockIdx.x * 256 + t;
    int v = (i < NN) ? g_cnt[i] : 0;
    sh[t] = v;
    __syncthreads();
    #pragma unroll
    for (int off = 1; off < 256; off <<= 1) {
        int tv = (t >= off) ? sh[t - off] : 0;
        __syncthreads();
        sh[t] += tv;
        __syncthreads();
    }
    if (i < NN) g_rowptr[i] = g_boff[blockIdx.x] + sh[t] - v;
}

__global__ void k_fill(const void* __restrict__ ei) {
    int i = blockIdx.x * blockDim.x + threadIdx.x;
    if (i >= ENT) return;
    int s, d;
    if (i < EE) { s = load_idx(ei, i); d = load_idx(ei, (long long)EE + i); }
    else        { s = d = i - EE; }
    int pos = atomicAdd(&g_cursor[d], 1);
    int idx = g_rowptr[d] + pos;
    g_col[idx] = s;
    g_w[idx]   = g_dinv[s] * g_dinv[d];
}

// ---------------- converters ----------------
// fp32 -> bf16 (MODE 0: -> g_X16, MODE 1: -> g_W16)
template<int MODE>
__global__ __launch_bounds__(256) void k_cvt16(const float* __restrict__ src, int n4) {
    int i = blockIdx.x * blockDim.x + threadIdx.x;
    if (i >= n4) return;
    float4 v = ((const float4*)src)[i];
    __nv_bfloat16* dst = (MODE == 0) ? g_X16 : g_W16;
    __nv_bfloat162* p = (__nv_bfloat162*)(dst + (size_t)i * 4);
    p[0] = __floats2bfloat162_rn(v.x, v.y);
    p[1] = __floats2bfloat162_rn(v.z, v.w);
}

// ---------------- tensor-core GEMM ----------------
// g_M8[N,256] = e4m3( A[N,K] @ W16[K,256] ); fp32 accum, single bf16 MMA term.
__device__ __forceinline__ void ldsm_x4(unsigned* r, const void* p) {
    unsigned a = (unsigned)__cvta_generic_to_shared(p);
    asm volatile("ldmatrix.sync.aligned.m8n8.x4.shared.b16 {%0,%1,%2,%3}, [%4];"
                 : "=r"(r[0]), "=r"(r[1]), "=r"(r[2]), "=r"(r[3]) : "r"(a));
}
__device__ __forceinline__ void ldsm_x4t(unsigned* r, const void* p) {
    unsigned a = (unsigned)__cvta_generic_to_shared(p);
    asm volatile("ldmatrix.sync.aligned.m8n8.x4.trans.shared.b16 {%0,%1,%2,%3}, [%4];"
                 : "=r"(r[0]), "=r"(r[1]), "=r"(r[2]), "=r"(r[3]) : "r"(a));
}
__device__ __forceinline__ void mma_bf16(float* c, const unsigned* a, const unsigned* b) {
    asm volatile("mma.sync.aligned.m16n8k16.row.col.f32.bf16.bf16.f32 "
                 "{%0,%1,%2,%3}, {%4,%5,%6,%7}, {%8,%9}, {%0,%1,%2,%3};"
                 : "+f"(c[0]), "+f"(c[1]), "+f"(c[2]), "+f"(c[3])
                 : "r"(a[0]), "r"(a[1]), "r"(a[2]), "r"(a[3]), "r"(b[0]), "r"(b[1]));
}

#define ASTRIDE 40    // 32 + 8 pad (bf16)
#define BSTRIDE 136   // 128 + 8 pad (bf16)

// FIRST=true -> A = g_X16 (K=512); else A = g_H16 (K=256)
template<int K, bool FIRST>
__global__ __launch_bounds__(256) void k_gemm_mma() {
    __shared__ __nv_bfloat16 As[128 * ASTRIDE];
    __shared__ __nv_bfloat16 Bs[32 * BSTRIDE];

    int t      = threadIdx.x;
    int lane   = t & 31;
    int wid    = t >> 5;
    int warp_m = wid >> 2;       // 0..1 -> 64-row band
    int warp_n = wid & 3;        // 0..3 -> 32-col band
    int col0   = blockIdx.x * 128;
    int row0   = blockIdx.y * 128;

    const __nv_bfloat16* A = FIRST ? g_X16 : g_H16;

    float acc[4][4][4];
    #pragma unroll
    for (int mt = 0; mt < 4; mt++)
        #pragma unroll
        for (int nt = 0; nt < 4; nt++)
            #pragma unroll
            for (int r = 0; r < 4; r++) acc[mt][nt][r] = 0.f;

    for (int k0 = 0; k0 < K; k0 += 32) {
        // ---- load A tile: 128 rows x 32 bf16 = 512 uint4 ----
        #pragma unroll
        for (int u = 0; u < 2; u++) {
            int idx = t + u * 256;
            int m   = idx >> 2;
            int q   = idx & 3;
            int gr  = row0 + m;
            uint4 v = make_uint4(0u, 0u, 0u, 0u);
            if (gr < NN)
                v = *(const uint4*)(A + (size_t)gr * K + k0 + q * 8);
            *(uint4*)(As + m * ASTRIDE + q * 8) = v;
        }
        // ---- load B tile: 32 rows x 128 bf16 = 512 uint4 ----
        #pragma unroll
        for (int u = 0; u < 2; u++) {
            int idx = t + u * 256;
            int kk  = idx >> 4;
            int q   = idx & 15;
            *(uint4*)(Bs + kk * BSTRIDE + q * 8) =
                *(const uint4*)(g_W16 + (size_t)(k0 + kk) * HH + col0 + q * 8);
        }
        __syncthreads();

        #pragma unroll
        for (int ks = 0; ks < 2; ks++) {
            unsigned ah[4][4], bh[4][2];
            int ar = lane & 15;
            int ac = (lane >> 4) * 8;
            #pragma unroll
            for (int mt = 0; mt < 4; mt++)
                ldsm_x4(ah[mt], As + (warp_m * 64 + mt * 16 + ar) * ASTRIDE + ks * 16 + ac);
            int bg  = lane >> 3;
            int brw = ks * 16 + (bg & 1) * 8 + (lane & 7);
            #pragma unroll
            for (int p = 0; p < 2; p++) {
                int bc = warp_n * 32 + p * 16 + (bg >> 1) * 8;
                unsigned tmp[4];
                ldsm_x4t(tmp, Bs + brw * BSTRIDE + bc);
                bh[p * 2][0] = tmp[0]; bh[p * 2][1] = tmp[1];
                bh[p * 2 + 1][0] = tmp[2]; bh[p * 2 + 1][1] = tmp[3];
            }
            #pragma unroll
            for (int mt = 0; mt < 4; mt++)
                #pragma unroll
                for (int nt = 0; nt < 4; nt++)
                    mma_bf16(acc[mt][nt], ah[mt], bh[nt]);
        }
        __syncthreads();
    }

    // epilogue: e4m3 store to g_M8 (2 bytes per register pair)
    #pragma unroll
    for (int mt = 0; mt < 4; mt++) {
        int gr0 = row0 + warp_m * 64 + mt * 16 + (lane >> 2);
        #pragma unroll
        for (int nt = 0; nt < 4; nt++) {
            int gc = col0 + warp_n * 32 + nt * 8 + (lane & 3) * 2;
            if (gr0 < NN) {
                __nv_fp8x2_storage_t p01 = __nv_cvt_float2_to_fp8x2(
                    make_float2(acc[mt][nt][0], acc[mt][nt][1]), __NV_SATFINITE, __NV_E4M3);
                *(unsigned short*)(g_M8 + (size_t)gr0 * HH + gc) = p01;
            }
            if (gr0 + 8 < NN) {
                __nv_fp8x2_storage_t p23 = __nv_cvt_float2_to_fp8x2(
                    make_float2(acc[mt][nt][2], acc[mt][nt][3]), __NV_SATFINITE, __NV_E4M3);
                *(unsigned short*)(g_M8 + (size_t)(gr0 + 8) * HH + gc) = p23;
            }
        }
    }
}

// ---------------- CSR gather aggregation (e4m3 in, bf16 out, fp32 accum) ----------------
// one block per dst node; 64 threads, each owns 4 columns (one 4-byte fp8 quad)
template<int DO_RELU>
__global__ __launch_bounds__(64) void k_agg(const float* __restrict__ bias) {
    int n  = blockIdx.x;
    int c4 = threadIdx.x;            // 0..63 -> cols [4c4, 4c4+3]
    int start = g_rowptr[n];
    int end   = g_rowptr[n + 1];
    __shared__ int   scol[64];
    __shared__ float sw[64];
    const unsigned* m = (const unsigned*)g_M8;
    float4 a0 = make_float4(0.f, 0.f, 0.f, 0.f), a1 = a0;
    for (int e0 = start; e0 < end; e0 += 64) {
        int cnt = min(64, end - e0);
        if (c4 < cnt) { scol[c4] = g_col[e0 + c4]; sw[c4] = g_w[e0 + c4]; }
        __syncthreads();
        int j = 0;
        for (; j + 2 <= cnt; j += 2) {
            unsigned v0 = __ldg(m + (size_t)scol[j + 0] * 64 + c4);
            unsigned v1 = __ldg(m + (size_t)scol[j + 1] * 64 + c4);
            float w0 = sw[j + 0], w1 = sw[j + 1];
            __half2_raw h0a = __nv_cvt_fp8x2_to_halfraw2((__nv_fp8x2_storage_t)(v0 & 0xFFFF), __NV_E4M3);
            __half2_raw h0b = __nv_cvt_fp8x2_to_halfraw2((__nv_fp8x2_storage_t)(v0 >> 16), __NV_E4M3);
            __half2_raw h1a = __nv_cvt_fp8x2_to_halfraw2((__nv_fp8x2_storage_t)(v1 & 0xFFFF), __NV_E4M3);
            __half2_raw h1b = __nv_cvt_fp8x2_to_halfraw2((__nv_fp8x2_storage_t)(v1 >> 16), __NV_E4M3);
            float2 f0a = __half22float2(h0a), f0b = __half22float2(h0b);
            float2 f1a = __half22float2(h1a), f1b = __half22float2(h1b);
            a0.x = fmaf(f0a.x, w0, a0.x); a0.y = fmaf(f0a.y, w0, a0.y);
            a0.z = fmaf(f0b.x, w0, a0.z); a0.w = fmaf(f0b.y, w0, a0.w);
            a1.x = fmaf(f1a.x, w1, a1.x); a1.y = fmaf(f1a.y, w1, a1.y);
            a1.z = fmaf(f1b.x, w1, a1.z); a1.w = fmaf(f1b.y, w1, a1.w);
        }
        for (; j < cnt; j++) {
            unsigned v = __ldg(m + (size_t)scol[j] * 64 + c4);
            float w = sw[j];
            __half2_raw ha = __nv_cvt_fp8x2_to_halfraw2((__nv_fp8x2_storage_t)(v & 0xFFFF), __NV_E4M3);
            __half2_raw hb = __nv_cvt_fp8x2_to_halfraw2((__nv_fp8x2_storage_t)(v >> 16), __NV_E4M3);
            float2 fa = __half22float2(ha), fb = __half22float2(hb);
            a0.x = fmaf(fa.x, w, a0.x); a0.y = fmaf(fa.y, w, a0.y);
            a0.z = fmaf(fb.x, w, a0.z); a0.w = fmaf(fb.y, w, a0.w);
        }
        __syncthreads();
    }
    float r0 = a0.x + a1.x + bias[4 * c4 + 0];
    float r1 = a0.y + a1.y + bias[4 * c4 + 1];
    float r2 = a0.z + a1.z + bias[4 * c4 + 2];
    float r3 = a0.w + a1.w + bias[4 * c4 + 3];
    if (DO_RELU) {
        r0 = fmaxf(r0, 0.f); r1 = fmaxf(r1, 0.f);
        r2 = fmaxf(r2, 0.f); r3 = fmaxf(r3, 0.f);
    }
    __nv_bfloat162* hp = (__nv_bfloat162*)(g_H16 + (size_t)n * HH + 4 * c4);
    hp[0] = __floats2bfloat162_rn(r0, r1);
    hp[1] = __floats2bfloat162_rn(r2, r3);
}

// ---------------- pooling ----------------
__global__ void k_zero_pool() {
    int i = blockIdx.x * blockDim.x + threadIdx.x;
    if (i < GG * HH) g_pooled[i] = 0.f;
    if (i < GG) g_gcount[i] = 0;
}

// block = 64 nodes x 128 col-pairs; batch sorted -> few boundaries per chunk
__global__ __launch_bounds__(128) void k_pool(const void* __restrict__ batch) {
    int base = blockIdx.x * 64;
    int c2 = threadIdx.x;
    __shared__ int sg[64];
    int nmax = min(64, NN - base);
    if (nmax <= 0) return;
    if (c2 < nmax) sg[c2] = load_gidx(batch, base + c2);
    __syncthreads();
    const __nv_bfloat162* h = (const __nv_bfloat162*)g_H16;
    int gprev = sg[0];
    float2 acc = make_float2(0.f, 0.f);
    for (int i = 0; i < nmax; i++) {
        int g = sg[i];
        if (g != gprev) {
            atomicAdd(&g_pooled[gprev * HH + 2 * c2], acc.x);
            atomicAdd(&g_pooled[gprev * HH + 2 * c2 + 1], acc.y);
            acc = make_float2(0.f, 0.f);
            gprev = g;
        }
        float2 v = __bfloat1622float2(h[(size_t)(base + i) * 128 + c2]);
        acc.x += v.x; acc.y += v.y;
    }
    atomicAdd(&g_pooled[gprev * HH + 2 * c2], acc.x);
    atomicAdd(&g_pooled[gprev * HH + 2 * c2 + 1], acc.y);
    if (c2 < nmax) atomicAdd(&g_gcount[sg[c2]], 1);
}

// ---------------- final MLP + sigmoid ----------------
__global__ __launch_bounds__(1024) void k_mlp(const float* __restrict__ Wf,
                                              const float* __restrict__ bf,
                                              const float* __restrict__ Wp,
                                              const float* __restrict__ bp,
                                              float* __restrict__ out) {
    __shared__ float pm[GG * HH];
    __shared__ float fsh[GG * 64];
    int t = threadIdx.x;
    for (int i = t; i < GG * HH; i += 1024) {
        int g = i / HH;
        float cnt = fmaxf((float)g_gcount[g], 1.f);
        pm[i] = g_pooled[i] / cnt;
    }
    __syncthreads();
    int g  = t >> 6;
    int oc = t & 63;
    float f = bf[oc];
    #pragma unroll 8
    for (int k = 0; k < HH; k++)
        f = fmaf(pm[g * HH + k], Wf[k * 64 + oc], f);
    fsh[g * 64 + oc] = f;
    __syncthreads();
    if (t < GG) {
        float o = bp[0];
        #pragma unroll
        for (int j = 0; j < 64; j++)
            o = fmaf(fsh[t * 64 + j], Wp[j], o);
        out[t] = 1.f / (1.f + expf(-o));
    }
}

// ---------------- launch ----------------
extern "C" void kernel_launch(void* const* d_in, const int* in_sizes, int n_in,
                              void* d_out, int out_size) {
    const float* x     = (const float*)d_in[0];
    const void*  ei    = d_in[1];   // [2, E] int32 or int64 (probed on device)
    const void*  batch = d_in[2];
    const float* W1 = (const float*)d_in[3];
    const float* b1 = (const float*)d_in[4];
    const float* W2 = (const float*)d_in[5];
    const float* b2 = (const float*)d_in[6];
    const float* W3 = (const float*)d_in[7];
    const float* b3 = (const float*)d_in[8];
    const float* Wf = (const float*)d_in[9];
    const float* bf = (const float*)d_in[10];
    const float* Wp = (const float*)d_in[11];
    const float* bp = (const float*)d_in[12];
    float* out = (float*)d_out;

    // graph setup
    k_probe<<<1, 256>>>((const unsigned int*)ei);
    k_init_cnt<<<SCAN_B, 256>>>();
    k_count<<<(EE + 255) / 256, 256>>>(ei);
    k_dinv<<<SCAN_B, 256>>>();
    k_scan1<<<SCAN_B, 256>>>();
    k_scan2<<<1, 256>>>();
    k_scan3<<<SCAN_B, 256>>>();
    k_fill<<<(ENT + 255) / 256, 256>>>(ei);

    dim3 ggrid(2, (NN + 127) / 128);
    const int nA1 = NN * DIN / 4;
    const int nW1 = DIN * HH / 4, nW2 = HH * HH / 4;

    k_cvt16<0><<<(nA1 + 255) / 256, 256>>>(x, nA1);

    // layer 1
    k_cvt16<1><<<(nW1 + 255) / 256, 256>>>(W1, nW1);
    k_gemm_mma<DIN, true><<<ggrid, 256>>>();
    k_agg<1><<<NN, 64>>>(b1);
    // layer 2
    k_cvt16<1><<<(nW2 + 255) / 256, 256>>>(W2, nW2);
    k_gemm_mma<HH, false><<<ggrid, 256>>>();
    k_agg<1><<<NN, 64>>>(b2);
    // layer 3
    k_cvt16<1><<<(nW2 + 255) / 256, 256>>>(W3, nW2);
    k_gemm_mma<HH, false><<<ggrid, 256>>>();
    k_agg<0><<<NN, 64>>>(b3);

    // pooling + head
    k_zero_pool<<<(GG * HH + 255) / 256, 256>>>();
    k_pool<<<(NN + 63) / 64, 128>>>(batch);
    k_mlp<<<1, 1024>>>(Wf, bf, Wp, bp, out);
}